// round 13
// baseline (speedup 1.0000x reference)
#include <cuda_runtime.h>
#include <cuda_fp16.h>

#define NB 32
#define C  64
#define T  64
#define V  128
#define KK 128   // RED*T

// Scratch (allocation-free rule: __device__ globals)
// xf layout: [n][t][c][v]  (contiguous 16KB slab per (n,t))
__device__ __half g_xf_h[(size_t)NB*C*T*V];     // 34 MB
__device__ float  g_a  [(size_t)NB*KK*V];       // 2 MB
__device__ float  g_b  [(size_t)NB*KK*V];       // 2 MB
__device__ __half g_xm_h[(size_t)NB*T*V*V];     // 67 MB

__device__ __forceinline__ float tanh_fast(float x){
    float y; asm("tanh.approx.f32 %0, %1;" : "=f"(y) : "f"(x)); return y;
}
__device__ __forceinline__ unsigned smem_u32(const void* p){
    return (unsigned)__cvta_generic_to_shared(p);
}
__device__ __forceinline__ void ldm_x4(unsigned addr, unsigned& r0, unsigned& r1,
                                       unsigned& r2, unsigned& r3){
    asm volatile("ldmatrix.sync.aligned.m8n8.x4.shared.b16 {%0,%1,%2,%3}, [%4];"
                 : "=r"(r0), "=r"(r1), "=r"(r2), "=r"(r3) : "r"(addr));
}
__device__ __forceinline__ void ldm_x2t(unsigned addr, unsigned& r0, unsigned& r1){
    asm volatile("ldmatrix.sync.aligned.m8n8.x2.trans.shared.b16 {%0,%1}, [%2];"
                 : "=r"(r0), "=r"(r1) : "r"(addr));
}
__device__ __forceinline__ void mma16816(float* c, const unsigned* a, const unsigned* b){
    asm volatile("mma.sync.aligned.m16n8k16.row.col.f32.f16.f16.f32 "
                 "{%0,%1,%2,%3}, {%4,%5,%6,%7}, {%8,%9}, {%0,%1,%2,%3};"
                 : "+f"(c[0]), "+f"(c[1]), "+f"(c[2]), "+f"(c[3])
                 : "r"(a[0]), "r"(a[1]), "r"(a[2]), "r"(a[3]),
                   "r"(b[0]), "r"(b[1]));
}
__device__ __forceinline__ uint4 f8_to_h8(float4 f0, float4 f1){
    __half2 h0 = __floats2half2_rn(f0.x, f0.y);
    __half2 h1 = __floats2half2_rn(f0.z, f0.w);
    __half2 h2 = __floats2half2_rn(f1.x, f1.y);
    __half2 h3 = __floats2half2_rn(f1.z, f1.w);
    uint4 p;
    p.x = *(unsigned*)&h0; p.y = *(unsigned*)&h1;
    p.z = *(unsigned*)&h2; p.w = *(unsigned*)&h3;
    return p;
}
__device__ __forceinline__ void cp16(unsigned dst, const void* src){
    asm volatile("cp.async.cg.shared.global [%0], [%1], 16;"
                 :: "r"(dst), "l"(src));
}
__device__ __forceinline__ void cp_commit(){
    asm volatile("cp.async.commit_group;");
}
template<int N>
__device__ __forceinline__ void cp_wait(){
    asm volatile("cp.async.wait_group %0;" :: "n"(N));
}

// ---------------------------------------------------------------------------
// Kernel 1 (tensor-core): per (n,t):
//   xf[64c x 128v] = Wf[64x64] @ x[64x128] + bf   (fp16 operands, fp32 acc)
//   a/b[2 x 128v]  = Wm{1,2}[2x64] @ x + bm       (fp32, x re-read via L1)
// grid (T, NB), 256 threads (8 warps). xf stored [n][t][c][v].
// ---------------------------------------------------------------------------
__global__ __launch_bounds__(256) void k1(
    const float* __restrict__ x,  const float* __restrict__ Wf,
    const float* __restrict__ bf, const float* __restrict__ Wm1,
    const float* __restrict__ bm1,const float* __restrict__ Wm2,
    const float* __restrict__ bm2)
{
    __shared__ __align__(16) __half xh[C][V];      // 16 KB swizzled (B operand)
    __shared__ __align__(16) __half wf_s[C][C];    // 8 KB swizzled (A operand)
    __shared__ float wm1s[2][C];
    __shared__ float wm2s[2][C];
    __shared__ float bf_s[C];

    const int t = blockIdx.x, n = blockIdx.y;
    const int tid = threadIdx.x;
    const int lane = tid & 31, warp = tid >> 5;

    if (tid < 128){ ((float*)wm1s)[tid] = Wm1[tid]; ((float*)wm2s)[tid] = Wm2[tid]; }
    if (tid < 64) bf_s[tid] = bf[tid];

    // load x tile [64c x 128v] -> fp16 swizzled
    const float* xbase = x + (((size_t)n*C)*T + t)*V;
#pragma unroll
    for (int i = 0; i < 4; i++){
        int idx = i*256 + tid; int c = idx >> 4; int u = idx & 15;
        const float* src = xbase + (size_t)c*T*V + u*8;
        float4 f0 = *(const float4*)(src);
        float4 f1 = *(const float4*)(src + 4);
        *(uint4*)&xh[c][(u ^ (c & 7)) << 3] = f8_to_h8(f0, f1);
    }
    // load Wf [64 x 64] -> fp16 swizzled
#pragma unroll
    for (int i = 0; i < 2; i++){
        int idx = i*256 + tid; int o = idx >> 3; int u = idx & 7;
        const float* src = Wf + (size_t)o*C + u*8;
        float4 f0 = *(const float4*)(src);
        float4 f1 = *(const float4*)(src + 4);
        *(uint4*)&wf_s[o][(u ^ (o & 7)) << 3] = f8_to_h8(f0, f1);
    }

    // barrier: wm1s/wm2s visible to all + xh/wf_s/bf_s published
    __syncthreads();

    // a/b in fp32: re-read x (L1-resident), vectorized float4, 64 threads
    if (tid < 64){
        const int rr = tid >> 5, vg = tid & 31;
        float a0 = bm1[rr], a1 = a0, a2 = a0, a3 = a0;
        float b0 = bm2[rr], b1 = b0, b2 = b0, b3 = b0;
        const float* xp = xbase + vg*4;
#pragma unroll 8
        for (int c = 0; c < C; c++){
            float4 xv = *(const float4*)(xp + (size_t)c*T*V);
            float w1 = wm1s[rr][c], w2 = wm2s[rr][c];
            a0 = fmaf(w1, xv.x, a0); a1 = fmaf(w1, xv.y, a1);
            a2 = fmaf(w1, xv.z, a2); a3 = fmaf(w1, xv.w, a3);
            b0 = fmaf(w2, xv.x, b0); b1 = fmaf(w2, xv.y, b1);
            b2 = fmaf(w2, xv.z, b2); b3 = fmaf(w2, xv.w, b3);
        }
        *(float4*)&g_a[((size_t)n*KK + rr*T + t)*V + vg*4] = make_float4(a0,a1,a2,a3);
        *(float4*)&g_b[((size_t)n*KK + rr*T + t)*V + vg*4] = make_float4(b0,b1,b2,b3);
    }

    const int wm = warp & 1, wn = warp >> 1;
    const unsigned wf_base = smem_u32(&wf_s[0][0]);
    const unsigned xh_base = smem_u32(&xh[0][0]);

    float acc[2][4][4];
#pragma unroll
    for (int i = 0; i < 2; i++)
#pragma unroll
        for (int j = 0; j < 4; j++)
#pragma unroll
            for (int q = 0; q < 4; q++) acc[i][j][q] = 0.f;

#pragma unroll
    for (int kc = 0; kc < 4; kc++){
        unsigned afr[2][4];
#pragma unroll
        for (int mtl = 0; mtl < 2; mtl++){
            int row = wm*32 + mtl*16 + (lane & 15);
            unsigned addr = wf_base + row*128 +
                (((kc*2 + (lane >> 4)) ^ (row & 7)) << 4);
            ldm_x4(addr, afr[mtl][0], afr[mtl][1], afr[mtl][2], afr[mtl][3]);
        }
        unsigned bfr[4][2];
        {
            int row = kc*16 + (lane & 15);
            unsigned rb = xh_base + row*256;
#pragma unroll
            for (int ntl = 0; ntl < 4; ntl++){
                unsigned addr = rb + ((((wn << 2) + ntl) ^ (row & 7)) << 4);
                ldm_x2t(addr, bfr[ntl][0], bfr[ntl][1]);
            }
        }
#pragma unroll
        for (int mtl = 0; mtl < 2; mtl++)
#pragma unroll
            for (int ntl = 0; ntl < 4; ntl++)
                mma16816(acc[mtl][ntl], afr[mtl], bfr[ntl]);
    }

    // epilogue: + bf, stage through xh (reuse), then coalesced 16B stores
    __syncthreads();   // all ldmatrix reads of xh complete
#pragma unroll
    for (int mtl = 0; mtl < 2; mtl++){
#pragma unroll
        for (int ntl = 0; ntl < 4; ntl++){
            int c0 = wm*32 + mtl*16 + (lane >> 2);
            int v  = (wn << 5) + (ntl << 3) + ((lane & 3) << 1);
#pragma unroll
            for (int h = 0; h < 2; h++){
                int cc = c0 + h*8;
                float r0 = acc[mtl][ntl][2*h]     + bf_s[cc];
                float r1 = acc[mtl][ntl][2*h + 1] + bf_s[cc];
                int hc = (v >> 1) ^ ((cc & 7) << 3);
                ((__half2*)&xh[cc][0])[hc] = __floats2half2_rn(r0, r1);
            }
        }
    }
    __syncthreads();
    {
        __half* dst = g_xf_h + ((size_t)n*T + t)*C*V;
#pragma unroll
        for (int i = 0; i < 4; i++){
            int idx = i*256 + tid; int cc = idx >> 4; int q = idx & 15;
            int qs = q ^ ((cc & 7) << 1);
            *(uint4*)(dst + (size_t)cc*V + q*8) = ((uint4*)&xh[cc][0])[qs];
        }
    }
}

// ---------------------------------------------------------------------------
// Kernel 2 (tensor-core): per block: 16v x 16w tile of xm for one n.
// D[64t x 256(vw)] = Wrm[64x128] @ E[128 x 256], E = tanh(a[k,v]-b[k,w]),
// generated on the fly into double-buffered fp16 smem.
// E-gen: thread=(k-row r, v-col vi) computes 16 w values -> two STS.128.
// smem exactly 48 KB. grid (wt=8, vt=8, n=32), 256 threads (8 warps).
// ---------------------------------------------------------------------------
__global__ __launch_bounds__(256, 2) void k2(
    const float* __restrict__ Wrm, const float* __restrict__ brm,
    const float* __restrict__ Ag)
{
    __shared__ float a_s[KK][16];                       // 8 KB
    __shared__ float b_s[KK][16];                       // 8 KB
    __shared__ __align__(16) __half wrm_s[T][KK];       // 16 KB (swizzled)
    __shared__ __align__(16) __half Et[2][16][256];     // 16 KB (swizzled)

    const int wt = blockIdx.x, vt = blockIdx.y, n = blockIdx.z;
    const int tid = threadIdx.x;
    const int lane = tid & 31, warp = tid >> 5;

#pragma unroll
    for (int i = 0; i < 8; i++){
        int idx = i*256 + tid; int k = idx >> 4; int p = idx & 15;
        a_s[k][p] = g_a[((size_t)n*KK + k)*V + vt*16 + p];
        b_s[k][p] = g_b[((size_t)n*KK + k)*V + wt*16 + p];
    }
#pragma unroll
    for (int i = 0; i < 32; i++){
        int idx = i*256 + tid; int tt = idx >> 7; int kk = idx & 127;
        wrm_s[tt][(kk & 7) + ((((kk >> 3) ^ (tt & 7))) << 3)] =
            __float2half(Wrm[(size_t)tt*KK + kk]);
    }

    const int r = tid >> 4, vi = tid & 15;   // gen role: k-row r, v-col vi

    float acc[4][4][4];
#pragma unroll
    for (int i = 0; i < 4; i++)
#pragma unroll
        for (int j = 0; j < 4; j++)
#pragma unroll
            for (int q = 0; q < 4; q++) acc[i][j][q] = 0.f;

    const unsigned wrm_base = smem_u32(&wrm_s[0][0]);
    const unsigned et_base  = smem_u32(&Et[0][0][0]);

    __syncthreads();

#pragma unroll
    for (int kc = 0; kc < 8; kc++){
        const int buf = kc & 1;
        // --- generate E chunk: thread computes tanh(a[k][vi]-b[k][wj]) wj=0..15,
        //     stores as two 16B vectors into the swizzled layout ---
        {
            const float av = a_s[kc*16 + r][vi];
            const float* brow = b_s[kc*16 + r];
            __half2 hv[8];
#pragma unroll
            for (int j = 0; j < 8; j++){
                float t0 = tanh_fast(av - brow[2*j]);
                float t1 = tanh_fast(av - brow[2*j + 1]);
                hv[j] = __floats2half2_rn(t0, t1);
            }
            __half* erow = &Et[buf][r][0];
            const int rsw = r & 7;
            *(uint4*)&erow[((vi*2    ) ^ rsw) << 3] = *(uint4*)&hv[0];
            *(uint4*)&erow[((vi*2 + 1) ^ rsw) << 3] = *(uint4*)&hv[4];
        }
        __syncthreads();
        // --- mma: A = Wrm chunk, B = E chunk ---
        unsigned afr[4][4];
#pragma unroll
        for (int mt = 0; mt < 4; mt++){
            int row = mt*16 + (lane & 15);
            unsigned addr = wrm_base + row*256 +
                (((kc*2 + (lane >> 4)) ^ (row & 7)) << 4);
            ldm_x4(addr, afr[mt][0], afr[mt][1], afr[mt][2], afr[mt][3]);
        }
        unsigned bfr[4][2];
        {
            int row = lane & 15;
            unsigned rb = et_base + buf*8192 + row*512;
#pragma unroll
            for (int ntl = 0; ntl < 4; ntl++){
                unsigned addr = rb + ((((warp << 2) + ntl) ^ (row & 7)) << 4);
                ldm_x2t(addr, bfr[ntl][0], bfr[ntl][1]);
            }
        }
#pragma unroll
        for (int mt = 0; mt < 4; mt++)
#pragma unroll
            for (int ntl = 0; ntl < 4; ntl++)
                mma16816(acc[mt][ntl], afr[mt], bfr[ntl]);
    }

    // --- epilogue: + brm + A, convert fp16, store xm ---
#pragma unroll
    for (int mt = 0; mt < 4; mt++){
#pragma unroll
        for (int ntl = 0; ntl < 4; ntl++){
            int t0 = mt*16 + (lane >> 2);
            int colbase = (warp << 5) + (ntl << 3) + ((lane & 3) << 1);
            int v   = vt*16 + (colbase >> 4);
            int wgl = wt*16 + (colbase & 15);
#pragma unroll
            for (int h = 0; h < 2; h++){
                int tt = t0 + h*8;
                float2 Av = *(const float2*)&Ag[((size_t)tt*V + v)*V + wgl];
                float br = __ldg(&brm[tt]);
                float r0 = acc[mt][ntl][2*h + 0] + br + Av.x;
                float r1 = acc[mt][ntl][2*h + 1] + br + Av.y;
                *(__half2*)&g_xm_h[(((size_t)n*T + tt)*V + v)*V + wgl] =
                    __floats2half2_rn(r0, r1);
            }
        }
    }
}

// ---------------------------------------------------------------------------
// Kernel 3 (tensor-core): per (n,t): out[64c x 128w] = xf[64x128] @ xm[128x128]
// xf = one contiguous 16KB slab (group 0); xm streamed through a 4-slot
// cp.async ring (4KB/slot), 3 chunks in flight. Epilogue staged through
// smem for coalesced STG.128. smem 32 KB. grid (T, NB), 256 threads.
// ---------------------------------------------------------------------------
__global__ __launch_bounds__(256) void k3(float* __restrict__ out)
{
    __shared__ __align__(16) unsigned char sraw[32768];
    __half (*xf_s)[V]     = (__half(*)[V])sraw;                 // 16 KB
    __half (*xm_r)[16][V] = (__half(*)[16][V])(sraw + 16384);   // 16 KB ring

    const int t = blockIdx.x, n = NB - 1 - blockIdx.y;
    const int tid = threadIdx.x;
    const int lane = tid & 31, warp = tid >> 5;

    const __half* xf_src = g_xf_h + ((size_t)n*T + t)*C*V;
    const __half* xm_src = g_xm_h + ((size_t)n*T + t)*V*V;
    const unsigned ring_base = smem_u32(&xm_r[0][0][0]);

    // group 0: all of xf (16 KB contiguous slab, 4 x 16B per thread)
#pragma unroll
    for (int i = 0; i < 4; i++){
        int idx = i*256 + tid; int c = idx >> 4; int u = idx & 15;
        cp16(smem_u32(&xf_s[c][(u ^ (c & 7)) << 3]), xf_src + (size_t)c*V + u*8);
    }
    cp_commit();

    const int rv = tid >> 4, uu = tid & 15;
    const unsigned ring_dst = ring_base + rv*256 + ((uu ^ (rv & 7)) << 4);
    // prologue: chunks 0..2
#pragma unroll
    for (int kc = 0; kc < 3; kc++){
        cp16(ring_dst + (kc & 3)*4096, xm_src + (size_t)(kc*16 + rv)*V + uu*8);
        cp_commit();
    }

    const int wm = warp & 1, wn = warp >> 1;
    const unsigned xf_base = smem_u32(&xf_s[0][0]);

    float acc[2][4][4];
#pragma unroll
    for (int i = 0; i < 2; i++)
#pragma unroll
        for (int j = 0; j < 4; j++)
#pragma unroll
            for (int q = 0; q < 4; q++) acc[i][j][q] = 0.f;

#pragma unroll
    for (int kc = 0; kc < 8; kc++){
        if      (kc < 6)  cp_wait<2>();
        else if (kc == 6) cp_wait<1>();
        else              cp_wait<0>();
        __syncthreads();

        if (kc + 3 < 8){
            cp16(ring_dst + ((kc + 3) & 3)*4096,
                 xm_src + (size_t)((kc + 3)*16 + rv)*V + uu*8);
            cp_commit();
        }

        unsigned afr[2][4];
#pragma unroll
        for (int mtl = 0; mtl < 2; mtl++){
            int row = wm*32 + mtl*16 + (lane & 15);
            unsigned addr = xf_base + row*256 +
                (((kc*2 + (lane >> 4)) ^ (row & 7)) << 4);
            ldm_x4(addr, afr[mtl][0], afr[mtl][1], afr[mtl][2], afr[mtl][3]);
        }
        unsigned bfr[4][2];
        {
            int rr = lane & 15;
            unsigned rb = ring_base + (kc & 3)*4096 + rr*256;
#pragma unroll
            for (int ntl = 0; ntl < 4; ntl++){
                unsigned addr = rb + ((((wn << 2) + ntl) ^ (rr & 7)) << 4);
                ldm_x2t(addr, bfr[ntl][0], bfr[ntl][1]);
            }
        }
#pragma unroll
        for (int mtl = 0; mtl < 2; mtl++)
#pragma unroll
            for (int ntl = 0; ntl < 4; ntl++)
                mma16816(acc[mtl][ntl], afr[mtl], bfr[ntl]);
    }

    // epilogue: stage fp32 tile in smem (reuse sraw, 32 KB), coalesced stores
    __syncthreads();   // mainloop smem reads complete; cp.async all drained
    {
        float (*ost)[V] = (float(*)[V])sraw;
#pragma unroll
        for (int mtl = 0; mtl < 2; mtl++){
#pragma unroll
            for (int ntl = 0; ntl < 4; ntl++){
                int c0 = wm*32 + mtl*16 + (lane >> 2);
                int w  = (wn << 5) + (ntl << 3) + ((lane & 3) << 1);
#pragma unroll
                for (int h = 0; h < 2; h++){
                    int cc = c0 + h*8;
                    int f2 = (w >> 1) ^ ((cc & 7) << 1);
                    ((float2*)&ost[cc][0])[f2] =
                        make_float2(acc[mtl][ntl][2*h], acc[mtl][ntl][2*h + 1]);
                }
            }
        }
        __syncthreads();
#pragma unroll
        for (int i = 0; i < 8; i++){
            int idx = i*256 + tid; int cc = idx >> 5; int g4 = idx & 31;
            float4 v4 = ((float4*)&ost[cc][0])[g4 ^ (cc & 7)];
            *(float4*)(out + (((size_t)n*C + cc)*T + t)*V + g4*4) = v4;
        }
    }
}

extern "C" void kernel_launch(void* const* d_in, const int* in_sizes, int n_in,
                              void* d_out, int out_size)
{
    const float* x   = (const float*)d_in[0];
    const float* A   = (const float*)d_in[1];
    const float* Wf  = (const float*)d_in[2];
    const float* bf  = (const float*)d_in[3];
    const float* Wm1 = (const float*)d_in[4];
    const float* bm1 = (const float*)d_in[5];
    const float* Wm2 = (const float*)d_in[6];
    const float* bm2 = (const float*)d_in[7];
    const float* Wrm = (const float*)d_in[8];
    const float* brm = (const float*)d_in[9];
    float* out = (float*)d_out;

    k1<<<dim3(T, NB), 256>>>(x, Wf, bf, Wm1, bm1, Wm2, bm2);
    k2<<<dim3(8, 8, NB), 256>>>(Wrm, brm, A);
    k3<<<dim3(T, NB), 256>>>(out);
}

// round 14
// speedup vs baseline: 1.0396x; 1.0396x over previous
#include <cuda_runtime.h>
#include <cuda_fp16.h>

#define NB 32
#define C  64
#define T  64
#define V  128
#define KK 128   // RED*T

// Scratch (allocation-free rule: __device__ globals)
// xf layout: [n][t][c][v]  (contiguous 16KB slab per (n,t))
__device__ __half g_xf_h[(size_t)NB*C*T*V];     // 34 MB
__device__ float  g_a  [(size_t)NB*KK*V];       // 2 MB
__device__ float  g_b  [(size_t)NB*KK*V];       // 2 MB
__device__ __half g_xm_h[(size_t)NB*T*V*V];     // 67 MB

__device__ __forceinline__ float tanh_fast(float x){
    float y; asm("tanh.approx.f32 %0, %1;" : "=f"(y) : "f"(x)); return y;
}
__device__ __forceinline__ unsigned smem_u32(const void* p){
    return (unsigned)__cvta_generic_to_shared(p);
}
__device__ __forceinline__ void ldm_x4(unsigned addr, unsigned& r0, unsigned& r1,
                                       unsigned& r2, unsigned& r3){
    asm volatile("ldmatrix.sync.aligned.m8n8.x4.shared.b16 {%0,%1,%2,%3}, [%4];"
                 : "=r"(r0), "=r"(r1), "=r"(r2), "=r"(r3) : "r"(addr));
}
__device__ __forceinline__ void ldm_x2t(unsigned addr, unsigned& r0, unsigned& r1){
    asm volatile("ldmatrix.sync.aligned.m8n8.x2.trans.shared.b16 {%0,%1}, [%2];"
                 : "=r"(r0), "=r"(r1) : "r"(addr));
}
__device__ __forceinline__ void mma16816(float* c, const unsigned* a, const unsigned* b){
    asm volatile("mma.sync.aligned.m16n8k16.row.col.f32.f16.f16.f32 "
                 "{%0,%1,%2,%3}, {%4,%5,%6,%7}, {%8,%9}, {%0,%1,%2,%3};"
                 : "+f"(c[0]), "+f"(c[1]), "+f"(c[2]), "+f"(c[3])
                 : "r"(a[0]), "r"(a[1]), "r"(a[2]), "r"(a[3]),
                   "r"(b[0]), "r"(b[1]));
}
__device__ __forceinline__ uint4 f8_to_h8(float4 f0, float4 f1){
    __half2 h0 = __floats2half2_rn(f0.x, f0.y);
    __half2 h1 = __floats2half2_rn(f0.z, f0.w);
    __half2 h2 = __floats2half2_rn(f1.x, f1.y);
    __half2 h3 = __floats2half2_rn(f1.z, f1.w);
    uint4 p;
    p.x = *(unsigned*)&h0; p.y = *(unsigned*)&h1;
    p.z = *(unsigned*)&h2; p.w = *(unsigned*)&h3;
    return p;
}
__device__ __forceinline__ void cp16(unsigned dst, const void* src){
    asm volatile("cp.async.cg.shared.global [%0], [%1], 16;"
                 :: "r"(dst), "l"(src));
}
__device__ __forceinline__ void cp_commit(){
    asm volatile("cp.async.commit_group;");
}
template<int N>
__device__ __forceinline__ void cp_wait(){
    asm volatile("cp.async.wait_group %0;" :: "n"(N));
}

// ---------------------------------------------------------------------------
// Kernel 1 (tensor-core): per (n,t):
//   xf[64c x 128v] = Wf[64x64] @ x[64x128] + bf   (fp16 operands, fp32 acc)
//   a/b[2 x 128v]  = Wm{1,2}[2x64] @ x + bm       (fp32, x re-read via L1)
// grid (T, NB), 256 threads (8 warps). xf stored [n][t][c][v].
// ---------------------------------------------------------------------------
__global__ __launch_bounds__(256) void k1(
    const float* __restrict__ x,  const float* __restrict__ Wf,
    const float* __restrict__ bf, const float* __restrict__ Wm1,
    const float* __restrict__ bm1,const float* __restrict__ Wm2,
    const float* __restrict__ bm2)
{
    __shared__ __align__(16) __half xh[C][V];      // 16 KB swizzled (B operand)
    __shared__ __align__(16) __half wf_s[C][C];    // 8 KB swizzled (A operand)
    __shared__ float wm1s[2][C];
    __shared__ float wm2s[2][C];
    __shared__ float bf_s[C];

    const int t = blockIdx.x, n = blockIdx.y;
    const int tid = threadIdx.x;
    const int lane = tid & 31, warp = tid >> 5;

    if (tid < 128){ ((float*)wm1s)[tid] = Wm1[tid]; ((float*)wm2s)[tid] = Wm2[tid]; }
    if (tid < 64) bf_s[tid] = bf[tid];

    // load x tile [64c x 128v] -> fp16 swizzled
    const float* xbase = x + (((size_t)n*C)*T + t)*V;
#pragma unroll
    for (int i = 0; i < 4; i++){
        int idx = i*256 + tid; int c = idx >> 4; int u = idx & 15;
        const float* src = xbase + (size_t)c*T*V + u*8;
        float4 f0 = *(const float4*)(src);
        float4 f1 = *(const float4*)(src + 4);
        *(uint4*)&xh[c][(u ^ (c & 7)) << 3] = f8_to_h8(f0, f1);
    }
    // load Wf [64 x 64] -> fp16 swizzled
#pragma unroll
    for (int i = 0; i < 2; i++){
        int idx = i*256 + tid; int o = idx >> 3; int u = idx & 7;
        const float* src = Wf + (size_t)o*C + u*8;
        float4 f0 = *(const float4*)(src);
        float4 f1 = *(const float4*)(src + 4);
        *(uint4*)&wf_s[o][(u ^ (o & 7)) << 3] = f8_to_h8(f0, f1);
    }

    // barrier: wm1s/wm2s visible to all + xh/wf_s/bf_s published
    __syncthreads();

    // a/b in fp32: re-read x (L1-resident), vectorized float4, 64 threads
    if (tid < 64){
        const int rr = tid >> 5, vg = tid & 31;
        float a0 = bm1[rr], a1 = a0, a2 = a0, a3 = a0;
        float b0 = bm2[rr], b1 = b0, b2 = b0, b3 = b0;
        const float* xp = xbase + vg*4;
#pragma unroll 8
        for (int c = 0; c < C; c++){
            float4 xv = *(const float4*)(xp + (size_t)c*T*V);
            float w1 = wm1s[rr][c], w2 = wm2s[rr][c];
            a0 = fmaf(w1, xv.x, a0); a1 = fmaf(w1, xv.y, a1);
            a2 = fmaf(w1, xv.z, a2); a3 = fmaf(w1, xv.w, a3);
            b0 = fmaf(w2, xv.x, b0); b1 = fmaf(w2, xv.y, b1);
            b2 = fmaf(w2, xv.z, b2); b3 = fmaf(w2, xv.w, b3);
        }
        *(float4*)&g_a[((size_t)n*KK + rr*T + t)*V + vg*4] = make_float4(a0,a1,a2,a3);
        *(float4*)&g_b[((size_t)n*KK + rr*T + t)*V + vg*4] = make_float4(b0,b1,b2,b3);
    }

    const int wm = warp & 1, wn = warp >> 1;
    const unsigned wf_base = smem_u32(&wf_s[0][0]);
    const unsigned xh_base = smem_u32(&xh[0][0]);

    float acc[2][4][4];
#pragma unroll
    for (int i = 0; i < 2; i++)
#pragma unroll
        for (int j = 0; j < 4; j++)
#pragma unroll
            for (int q = 0; q < 4; q++) acc[i][j][q] = 0.f;

#pragma unroll
    for (int kc = 0; kc < 4; kc++){
        unsigned afr[2][4];
#pragma unroll
        for (int mtl = 0; mtl < 2; mtl++){
            int row = wm*32 + mtl*16 + (lane & 15);
            unsigned addr = wf_base + row*128 +
                (((kc*2 + (lane >> 4)) ^ (row & 7)) << 4);
            ldm_x4(addr, afr[mtl][0], afr[mtl][1], afr[mtl][2], afr[mtl][3]);
        }
        unsigned bfr[4][2];
        {
            int row = kc*16 + (lane & 15);
            unsigned rb = xh_base + row*256;
#pragma unroll
            for (int ntl = 0; ntl < 4; ntl++){
                unsigned addr = rb + ((((wn << 2) + ntl) ^ (row & 7)) << 4);
                ldm_x2t(addr, bfr[ntl][0], bfr[ntl][1]);
            }
        }
#pragma unroll
        for (int mtl = 0; mtl < 2; mtl++)
#pragma unroll
            for (int ntl = 0; ntl < 4; ntl++)
                mma16816(acc[mtl][ntl], afr[mtl], bfr[ntl]);
    }

    // epilogue: + bf, stage through xh (reuse), then coalesced 16B stores
    __syncthreads();   // all ldmatrix reads of xh complete
#pragma unroll
    for (int mtl = 0; mtl < 2; mtl++){
#pragma unroll
        for (int ntl = 0; ntl < 4; ntl++){
            int c0 = wm*32 + mtl*16 + (lane >> 2);
            int v  = (wn << 5) + (ntl << 3) + ((lane & 3) << 1);
#pragma unroll
            for (int h = 0; h < 2; h++){
                int cc = c0 + h*8;
                float r0 = acc[mtl][ntl][2*h]     + bf_s[cc];
                float r1 = acc[mtl][ntl][2*h + 1] + bf_s[cc];
                int hc = (v >> 1) ^ ((cc & 7) << 3);
                ((__half2*)&xh[cc][0])[hc] = __floats2half2_rn(r0, r1);
            }
        }
    }
    __syncthreads();
    {
        __half* dst = g_xf_h + ((size_t)n*T + t)*C*V;
#pragma unroll
        for (int i = 0; i < 4; i++){
            int idx = i*256 + tid; int cc = idx >> 4; int q = idx & 15;
            int qs = q ^ ((cc & 7) << 1);
            *(uint4*)(dst + (size_t)cc*V + q*8) = ((uint4*)&xh[cc][0])[qs];
        }
    }
}

// ---------------------------------------------------------------------------
// Kernel 2 (tensor-core): per block: 16v x 16w tile of xm for one n.
// D[64t x 256(vw)] = Wrm[64x128] @ E[128 x 256], E = tanh(a[k,v]-b[k,w]),
// generated on the fly into double-buffered fp16 smem.
// Prologue fully vectorized (LDG.128 / STS.128). smem exactly 48 KB.
// grid (wt=8, vt=8, n=32), 256 threads (8 warps).
// ---------------------------------------------------------------------------
__global__ __launch_bounds__(256, 2) void k2(
    const float* __restrict__ Wrm, const float* __restrict__ brm,
    const float* __restrict__ Ag)
{
    __shared__ float a_s[KK][16];                       // 8 KB
    __shared__ float b_s[KK][16];                       // 8 KB
    __shared__ __align__(16) __half wrm_s[T][KK];       // 16 KB (swizzled)
    __shared__ __align__(16) __half Et[2][16][256];     // 16 KB (swizzled)

    const int wt = blockIdx.x, vt = blockIdx.y, n = blockIdx.z;
    const int tid = threadIdx.x;
    const int lane = tid & 31, warp = tid >> 5;

    // a_s/b_s: 128 rows x 16 floats, vectorized float4 (512 items, 2/thread)
#pragma unroll
    for (int i = 0; i < 2; i++){
        int idx = i*256 + tid; int k = idx >> 2; int p4 = idx & 3;
        ((float4*)&a_s[k][0])[p4] =
            *(const float4*)&g_a[((size_t)n*KK + k)*V + vt*16 + p4*4];
        ((float4*)&b_s[k][0])[p4] =
            *(const float4*)&g_b[((size_t)n*KK + k)*V + wt*16 + p4*4];
    }
    // Wrm: 64 rows x 128, in 8-element groups; group g of row tt lands at
    // contiguous halves [ (g^(tt&7))*8 .. +8 ). 1024 items, 4/thread.
#pragma unroll
    for (int i = 0; i < 4; i++){
        int idx = i*256 + tid; int tt = idx >> 4; int g = idx & 15;
        const float* src = Wrm + (size_t)tt*KK + g*8;
        float4 f0 = *(const float4*)(src);
        float4 f1 = *(const float4*)(src + 4);
        *(uint4*)&wrm_s[tt][(g ^ (tt & 7)) << 3] = f8_to_h8(f0, f1);
    }

    const int r = tid >> 4, vi = tid & 15;   // gen role: k-row r, v-col vi

    float acc[4][4][4];
#pragma unroll
    for (int i = 0; i < 4; i++)
#pragma unroll
        for (int j = 0; j < 4; j++)
#pragma unroll
            for (int q = 0; q < 4; q++) acc[i][j][q] = 0.f;

    const unsigned wrm_base = smem_u32(&wrm_s[0][0]);
    const unsigned et_base  = smem_u32(&Et[0][0][0]);

    __syncthreads();

#pragma unroll
    for (int kc = 0; kc < 8; kc++){
        const int buf = kc & 1;
        // --- generate E chunk: thread computes tanh(a[k][vi]-b[k][wj]) wj=0..15,
        //     stores as two 16B vectors into the swizzled layout ---
        {
            const float av = a_s[kc*16 + r][vi];
            const float* brow = b_s[kc*16 + r];
            __half2 hv[8];
#pragma unroll
            for (int j = 0; j < 8; j++){
                float t0 = tanh_fast(av - brow[2*j]);
                float t1 = tanh_fast(av - brow[2*j + 1]);
                hv[j] = __floats2half2_rn(t0, t1);
            }
            __half* erow = &Et[buf][r][0];
            const int rsw = r & 7;
            *(uint4*)&erow[((vi*2    ) ^ rsw) << 3] = *(uint4*)&hv[0];
            *(uint4*)&erow[((vi*2 + 1) ^ rsw) << 3] = *(uint4*)&hv[4];
        }
        __syncthreads();
        // --- mma: A = Wrm chunk, B = E chunk ---
        unsigned afr[4][4];
#pragma unroll
        for (int mt = 0; mt < 4; mt++){
            int row = mt*16 + (lane & 15);
            unsigned addr = wrm_base + row*256 +
                (((kc*2 + (lane >> 4)) ^ (row & 7)) << 4);
            ldm_x4(addr, afr[mt][0], afr[mt][1], afr[mt][2], afr[mt][3]);
        }
        unsigned bfr[4][2];
        {
            int row = lane & 15;
            unsigned rb = et_base + buf*8192 + row*512;
#pragma unroll
            for (int ntl = 0; ntl < 4; ntl++){
                unsigned addr = rb + ((((warp << 2) + ntl) ^ (row & 7)) << 4);
                ldm_x2t(addr, bfr[ntl][0], bfr[ntl][1]);
            }
        }
#pragma unroll
        for (int mt = 0; mt < 4; mt++)
#pragma unroll
            for (int ntl = 0; ntl < 4; ntl++)
                mma16816(acc[mt][ntl], afr[mt], bfr[ntl]);
    }

    // --- epilogue: + brm + A, convert fp16, store xm ---
#pragma unroll
    for (int mt = 0; mt < 4; mt++){
#pragma unroll
        for (int ntl = 0; ntl < 4; ntl++){
            int t0 = mt*16 + (lane >> 2);
            int colbase = (warp << 5) + (ntl << 3) + ((lane & 3) << 1);
            int v   = vt*16 + (colbase >> 4);
            int wgl = wt*16 + (colbase & 15);
#pragma unroll
            for (int h = 0; h < 2; h++){
                int tt = t0 + h*8;
                float2 Av = *(const float2*)&Ag[((size_t)tt*V + v)*V + wgl];
                float br = __ldg(&brm[tt]);
                float r0 = acc[mt][ntl][2*h + 0] + br + Av.x;
                float r1 = acc[mt][ntl][2*h + 1] + br + Av.y;
                *(__half2*)&g_xm_h[(((size_t)n*T + tt)*V + v)*V + wgl] =
                    __floats2half2_rn(r0, r1);
            }
        }
    }
}

// ---------------------------------------------------------------------------
// Kernel 3 (tensor-core): per (n,t): out[64c x 128w] = xf[64x128] @ xm[128x128]
// xf = one contiguous 16KB slab (group 0); xm streamed through a 4-slot
// cp.async ring (4KB/slot), 3 chunks in flight. Direct STG epilogue
// (smem-staged variant measured slower). smem 32 KB. grid (T, NB), 256 thr.
// ---------------------------------------------------------------------------
__global__ __launch_bounds__(256) void k3(float* __restrict__ out)
{
    __shared__ __align__(16) __half xf_s[C][V];        // 16 KB swizzled
    __shared__ __align__(16) __half xm_r[4][16][V];    // 16 KB ring (4 x 4KB)

    const int t = blockIdx.x, n = NB - 1 - blockIdx.y;
    const int tid = threadIdx.x;
    const int lane = tid & 31, warp = tid >> 5;

    const __half* xf_src = g_xf_h + ((size_t)n*T + t)*C*V;
    const __half* xm_src = g_xm_h + ((size_t)n*T + t)*V*V;
    const unsigned ring_base = smem_u32(&xm_r[0][0][0]);

    // group 0: all of xf (16 KB contiguous slab, 4 x 16B per thread)
#pragma unroll
    for (int i = 0; i < 4; i++){
        int idx = i*256 + tid; int c = idx >> 4; int u = idx & 15;
        cp16(smem_u32(&xf_s[c][(u ^ (c & 7)) << 3]), xf_src + (size_t)c*V + u*8);
    }
    cp_commit();

    const int rv = tid >> 4, uu = tid & 15;
    const unsigned ring_dst = ring_base + rv*256 + ((uu ^ (rv & 7)) << 4);
    // prologue: chunks 0..2
#pragma unroll
    for (int kc = 0; kc < 3; kc++){
        cp16(ring_dst + (kc & 3)*4096, xm_src + (size_t)(kc*16 + rv)*V + uu*8);
        cp_commit();
    }

    const int wm = warp & 1, wn = warp >> 1;
    const unsigned xf_base = smem_u32(&xf_s[0][0]);

    float acc[2][4][4];
#pragma unroll
    for (int i = 0; i < 2; i++)
#pragma unroll
        for (int j = 0; j < 4; j++)
#pragma unroll
            for (int q = 0; q < 4; q++) acc[i][j][q] = 0.f;

#pragma unroll
    for (int kc = 0; kc < 8; kc++){
        if      (kc < 6)  cp_wait<2>();
        else if (kc == 6) cp_wait<1>();
        else              cp_wait<0>();
        __syncthreads();

        if (kc + 3 < 8){
            cp16(ring_dst + ((kc + 3) & 3)*4096,
                 xm_src + (size_t)((kc + 3)*16 + rv)*V + uu*8);
            cp_commit();
        }

        unsigned afr[2][4];
#pragma unroll
        for (int mtl = 0; mtl < 2; mtl++){
            int row = wm*32 + mtl*16 + (lane & 15);
            unsigned addr = xf_base + row*256 +
                (((kc*2 + (lane >> 4)) ^ (row & 7)) << 4);
            ldm_x4(addr, afr[mtl][0], afr[mtl][1], afr[mtl][2], afr[mtl][3]);
        }
        unsigned bfr[4][2];
        {
            int rr = lane & 15;
            unsigned rb = ring_base + (kc & 3)*4096 + rr*256;
#pragma unroll
            for (int ntl = 0; ntl < 4; ntl++){
                unsigned addr = rb + ((((wn << 2) + ntl) ^ (rr & 7)) << 4);
                ldm_x2t(addr, bfr[ntl][0], bfr[ntl][1]);
            }
        }
#pragma unroll
        for (int mtl = 0; mtl < 2; mtl++)
#pragma unroll
            for (int ntl = 0; ntl < 4; ntl++)
                mma16816(acc[mtl][ntl], afr[mtl], bfr[ntl]);
    }

#pragma unroll
    for (int mtl = 0; mtl < 2; mtl++){
#pragma unroll
        for (int ntl = 0; ntl < 4; ntl++){
            int c0 = wm*32 + mtl*16 + (lane >> 2);
            int w  = (wn << 5) + (ntl << 3) + ((lane & 3) << 1);
#pragma unroll
            for (int h = 0; h < 2; h++){
                int cc = c0 + h*8;
                *(float2*)(out + (((size_t)n*C + cc)*T + t)*V + w) =
                    make_float2(acc[mtl][ntl][2*h], acc[mtl][ntl][2*h + 1]);
            }
        }
    }
}

extern "C" void kernel_launch(void* const* d_in, const int* in_sizes, int n_in,
                              void* d_out, int out_size)
{
    const float* x   = (const float*)d_in[0];
    const float* A   = (const float*)d_in[1];
    const float* Wf  = (const float*)d_in[2];
    const float* bf  = (const float*)d_in[3];
    const float* Wm1 = (const float*)d_in[4];
    const float* bm1 = (const float*)d_in[5];
    const float* Wm2 = (const float*)d_in[6];
    const float* bm2 = (const float*)d_in[7];
    const float* Wrm = (const float*)d_in[8];
    const float* brm = (const float*)d_in[9];
    float* out = (float*)d_out;

    k1<<<dim3(T, NB), 256>>>(x, Wf, bf, Wm1, bm1, Wm2, bm2);
    k2<<<dim3(8, 8, NB), 256>>>(Wrm, brm, A);
    k3<<<dim3(T, NB), 256>>>(out);
}